// round 15
// baseline (speedup 1.0000x reference)
#include <cuda_runtime.h>
#include <cuda_fp16.h>
#include <cstdint>

// ============================================================================
// RelationalPolicyHead: probs = softmax( relu([emb[s],emb[t]] @ W1 + b1) @ W2 + b2 )
//
// Factorization: A[n] = emb[n] @ W1[:128] + b1 ; B[n] = emb[n] @ W1[128:]
//   logit[e] = sum_j relu(A[s_e][j] + B[t_e][j]) * W2[j] + b2
// Precompute GEMM on tensor cores via mma.sync.m16n8k16 (fp16 in, fp32 accum).
// R12: CTA tile 64x256, warp tile 32x64, <=128 regs -> 2 blocks/SM (16 warps)
// to cure the latency-bound profile (occ 12.2%, issue 9.5% at R11).
// AB table stored FP16 (51 MB, L2-resident). Edge gathers evict_last.
// ============================================================================

#define HID 128
#define NMAX 100000
#define EMAX 1000000

__device__ __half d_AB16[(size_t)NMAX * 256];   // per node: [A(128) | B(128)] fp16
__device__ __half d_W1h[256 * 128];             // W1 as [n][k] row-major fp16
__device__ float d_logits[EMAX];
__device__ float d_partial[2048];
__device__ float d_partial2[2048];
__device__ unsigned d_flag;

typedef unsigned long long u64;
typedef unsigned int u32;

// ---- PTX helpers -----------------------------------------------------------
__device__ __forceinline__ u64 mkpolicy_el() {
    u64 p;
    asm("createpolicy.fractional.L2::evict_last.b64 %0, 1.0;" : "=l"(p));
    return p;
}
__device__ __forceinline__ uint2 ldg64_el(const __half* p, u64 pol) {
    uint2 v;
    asm("ld.global.nc.L2::cache_hint.v2.b32 {%0,%1}, [%2], %3;"
        : "=r"(v.x), "=r"(v.y) : "l"(p), "l"(pol));
    return v;
}
__device__ __forceinline__ float4 h4_to_f4(uint2 r) {
    __half2 h01 = *reinterpret_cast<__half2*>(&r.x);
    __half2 h23 = *reinterpret_cast<__half2*>(&r.y);
    float2 f01 = __half22float2(h01);
    float2 f23 = __half22float2(h23);
    return make_float4(f01.x, f01.y, f23.x, f23.y);
}
__device__ __forceinline__ u32 smem_u32(const void* p) {
    u32 a;
    asm("{ .reg .u64 t; cvta.to.shared.u64 t, %1; cvt.u32.u64 %0, t; }"
        : "=r"(a) : "l"(p));
    return a;
}
__device__ __forceinline__ void ldmx4(u32& r0, u32& r1, u32& r2, u32& r3, u32 addr) {
    asm volatile("ldmatrix.sync.aligned.m8n8.x4.shared.b16 {%0,%1,%2,%3}, [%4];"
                 : "=r"(r0), "=r"(r1), "=r"(r2), "=r"(r3) : "r"(addr));
}
__device__ __forceinline__ void mma16816(float* d, const u32* a, const u32* b) {
    asm volatile(
        "mma.sync.aligned.m16n8k16.row.col.f32.f16.f16.f32 "
        "{%0,%1,%2,%3}, {%4,%5,%6,%7}, {%8,%9}, {%0,%1,%2,%3};"
        : "+f"(d[0]), "+f"(d[1]), "+f"(d[2]), "+f"(d[3])
        : "r"(a[0]), "r"(a[1]), "r"(a[2]), "r"(a[3]), "r"(b[0]), "r"(b[1]));
}

// ---------------------------------------------------------------------------
__global__ void k_init() { d_flag = 0u; }

// detect index dtype: probe ONLY first 2E words (exist in both layouts).
__global__ void k_detect(const unsigned* __restrict__ lm32, int nwords) {
    unsigned acc = 0;
    int stride = gridDim.x * blockDim.x;
    int npairs = nwords >> 1;
    for (int i = blockIdx.x * blockDim.x + threadIdx.x; i < npairs; i += stride)
        acc |= __ldcs(&lm32[2 * i + 1]);
    #pragma unroll
    for (int o = 16; o; o >>= 1) acc |= __shfl_xor_sync(0xffffffffu, acc, o);
    if ((threadIdx.x & 31) == 0 && acc) atomicOr(&d_flag, acc);
}

// ---------------------------------------------------------------------------
// prep: W1 [256 x 128] fp32 -> fp16 [n][k] row-major.
// n<128: A half -> W1[k*128 + n]; n>=128: B half -> W1[(128+k)*128 + (n-128)]
__global__ void k_prepW(const float* __restrict__ W1) {
    int stride = gridDim.x * blockDim.x;
    for (int idx = blockIdx.x * blockDim.x + threadIdx.x; idx < 256 * 128; idx += stride) {
        int kglob = idx >> 7;        // W1 row in [0,256)
        int j = idx & 127;           // W1 col
        int n = (kglob < 128) ? j : (j + 128);
        int k = kglob & 127;
        d_W1h[n * 128 + k] = __float2half(__ldg(&W1[idx]));
    }
}

// ---------------------------------------------------------------------------
// GEMM: CTA tile 64 rows x 256 cols x K=128, fp16 mma.sync, fp32 accum.
// smem: A 64x128 fp16 (16KB, swizzled), B 256x128 fp16 (64KB, swizzled),
// b1 (512B) -> 82816 B/block; 2 blocks/SM. Warp tile 32x64 (8 warps: 2x4).
#define SM_A 0
#define SM_B 16384
#define SM_B1 (16384 + 65536)
#define GSMEM (16384 + 65536 + 512)

__global__ __launch_bounds__(256, 2)
void k_gemm(const float* __restrict__ emb,
            const float* __restrict__ b1,
            int nNodes) {
    extern __shared__ char smem[];
    const u32 sbase = smem_u32(smem);
    const int tid = threadIdx.x;
    const int wid = tid >> 5;
    const int lane = tid & 31;
    const int row0 = blockIdx.x * 64;

    // stage b1
    if (tid < 128) *((float*)(smem + SM_B1) + tid) = __ldg(&b1[tid]);

    // stage A: 64 rows, fp32->fp16, swizzled 16B chunks (idx = r*16 + (c^(r&7)))
    {
        uint4* aS = (uint4*)(smem + SM_A);
        #pragma unroll
        for (int q = tid; q < 64 * 16; q += 256) {
            int r = q >> 4, c = q & 15;
            int row = row0 + r;
            uint4 o;
            if (row < nNodes) {
                const float4* src = (const float4*)emb + (size_t)row * 32 + c * 2;
                float4 e0 = __ldcs(src);
                float4 e1 = __ldcs(src + 1);
                __half2 h0 = __floats2half2_rn(e0.x, e0.y);
                __half2 h1 = __floats2half2_rn(e0.z, e0.w);
                __half2 h2 = __floats2half2_rn(e1.x, e1.y);
                __half2 h3 = __floats2half2_rn(e1.z, e1.w);
                o.x = *reinterpret_cast<u32*>(&h0);
                o.y = *reinterpret_cast<u32*>(&h1);
                o.z = *reinterpret_cast<u32*>(&h2);
                o.w = *reinterpret_cast<u32*>(&h3);
            } else {
                o = make_uint4(0, 0, 0, 0);
            }
            aS[r * 16 + (c ^ (r & 7))] = o;
        }
    }
    // stage B: d_W1h (fp16 [n][k]), swizzled copy (L2-hot after first wave)
    {
        uint4* bS = (uint4*)(smem + SM_B);
        const uint4* src = (const uint4*)d_W1h;
        #pragma unroll
        for (int q = tid; q < 256 * 16; q += 256) {
            int r = q >> 4, c = q & 15;
            bS[r * 16 + (c ^ (r & 7))] = __ldg(&src[q]);
        }
    }
    __syncthreads();

    // warp tiling: rw = wid&1 (row group of 32), cw = wid>>1 (col group of 64)
    const int rwbase = (wid & 1) * 32;
    const int cwbase = (wid >> 1) * 64;
    const int j = lane >> 3;       // ldmatrix sub-matrix id
    const int i = lane & 7;        // row within sub-matrix

    const int rowA = rwbase + ((j & 1) << 3) + i;
    const int swA = rowA & 7;
    const int kjA = j >> 1;
    const int rowB = cwbase + ((j >> 1) << 3) + i;
    const int swB = rowB & 7;
    const int kjB = j & 1;

    float d[2][8][4];
    #pragma unroll
    for (int mt = 0; mt < 2; mt++)
        #pragma unroll
        for (int nt = 0; nt < 8; nt++)
            #pragma unroll
            for (int c = 0; c < 4; c++) d[mt][nt][c] = 0.f;

    #pragma unroll
    for (int ks = 0; ks < 8; ks++) {
        u32 af[2][4];
        #pragma unroll
        for (int mt = 0; mt < 2; mt++) {
            int row = rowA + mt * 16;
            u32 addr = sbase + SM_A + (u32)((row * 16 + ((2 * ks + kjA) ^ swA)) * 16);
            ldmx4(af[mt][0], af[mt][1], af[mt][2], af[mt][3], addr);
        }
        u32 bf[8][2];
        #pragma unroll
        for (int np = 0; np < 4; np++) {
            int row = rowB + np * 16;
            u32 addr = sbase + SM_B + (u32)((row * 16 + ((2 * ks + kjB) ^ swB)) * 16);
            u32 r0, r1, r2, r3;
            ldmx4(r0, r1, r2, r3, addr);
            bf[np * 2][0] = r0;     bf[np * 2][1] = r1;
            bf[np * 2 + 1][0] = r2; bf[np * 2 + 1][1] = r3;
        }
        #pragma unroll
        for (int mt = 0; mt < 2; mt++)
            #pragma unroll
            for (int nt = 0; nt < 8; nt++)
                mma16816(d[mt][nt], af[mt], bf[nt]);
    }

    // epilogue: thread holds (m = mt*16 + lane/4 (+8), n = nt*8 + 2*(lane%4) (+1))
    {
        const float* b1s = (const float*)(smem + SM_B1);
        const int qr = lane >> 2;
        const int tq = lane & 3;
        #pragma unroll
        for (int mt = 0; mt < 2; mt++) {
            #pragma unroll
            for (int half = 0; half < 2; half++) {
                int m = rwbase + mt * 16 + qr + half * 8;
                int grow = row0 + m;
                if (grow < nNodes) {
                    __half* dst = d_AB16 + (size_t)grow * 256;
                    #pragma unroll
                    for (int nt = 0; nt < 8; nt++) {
                        int n = cwbase + nt * 8 + (tq << 1);
                        float v0 = d[mt][nt][half * 2];
                        float v1 = d[mt][nt][half * 2 + 1];
                        if (n < 128) { v0 += b1s[n]; v1 += b1s[n + 1]; }
                        __half2 h = __floats2half2_rn(v0, v1);
                        *reinterpret_cast<__half2*>(dst + n) = h;
                    }
                }
            }
        }
    }
}

// ---------------------------------------------------------------------------
// edge kernel: warp per edge (2 in flight), fp16 gathers w/ evict_last.
__global__ __launch_bounds__(256, 8)
void k_edges(const unsigned* __restrict__ lm32,
             const float* __restrict__ W2, const float* __restrict__ b2, int E) {
    const int lane = threadIdx.x & 31;
    const int wl   = threadIdx.x >> 5;
    const int gw = (blockIdx.x * blockDim.x + threadIdx.x) >> 5;
    const int nw = (gridDim.x * blockDim.x) >> 5;
    const bool is64 = (d_flag == 0u);
    const u64 pol = mkpolicy_el();

    float4 w2 = __ldg((const float4*)W2 + lane);
    float bb2 = __ldg(b2);
    float lmax = -3.402823466e38f;

    for (int e0 = gw; e0 < E; e0 += 2 * nw) {
        int e1 = e0 + nw;
        bool has1 = (e1 < E);
        int ee1 = has1 ? e1 : e0;
        int s0, t0, s1, t1;
        if (is64) {
            s0 = (int)__ldcs(&lm32[2 * e0]);  t0 = (int)__ldcs(&lm32[2 * (E + e0)]);
            s1 = (int)__ldcs(&lm32[2 * ee1]); t1 = (int)__ldcs(&lm32[2 * (E + ee1)]);
        } else {
            s0 = (int)__ldcs(&lm32[e0]);      t0 = (int)__ldcs(&lm32[E + e0]);
            s1 = (int)__ldcs(&lm32[ee1]);     t1 = (int)__ldcs(&lm32[E + ee1]);
        }

        uint2 ra0 = ldg64_el(d_AB16 + (size_t)s0 * 256 + lane * 4, pol);
        uint2 rc0 = ldg64_el(d_AB16 + (size_t)t0 * 256 + 128 + lane * 4, pol);
        uint2 ra1 = ldg64_el(d_AB16 + (size_t)s1 * 256 + lane * 4, pol);
        uint2 rc1 = ldg64_el(d_AB16 + (size_t)t1 * 256 + 128 + lane * 4, pol);

        float4 a0 = h4_to_f4(ra0), c0 = h4_to_f4(rc0);
        float4 a1 = h4_to_f4(ra1), c1 = h4_to_f4(rc1);

        float acc0 = fmaxf(a0.x + c0.x, 0.f) * w2.x + fmaxf(a0.y + c0.y, 0.f) * w2.y
                   + fmaxf(a0.z + c0.z, 0.f) * w2.z + fmaxf(a0.w + c0.w, 0.f) * w2.w;
        float acc1 = fmaxf(a1.x + c1.x, 0.f) * w2.x + fmaxf(a1.y + c1.y, 0.f) * w2.y
                   + fmaxf(a1.z + c1.z, 0.f) * w2.z + fmaxf(a1.w + c1.w, 0.f) * w2.w;

        #pragma unroll
        for (int o = 16; o; o >>= 1) {
            acc0 += __shfl_xor_sync(0xffffffffu, acc0, o);
            acc1 += __shfl_xor_sync(0xffffffffu, acc1, o);
        }
        if (lane == 0) {
            float lg0 = acc0 + bb2;
            __stcs(&d_logits[e0], lg0);
            lmax = fmaxf(lmax, lg0);
            if (has1) {
                float lg1 = acc1 + bb2;
                __stcs(&d_logits[e1], lg1);
                lmax = fmaxf(lmax, lg1);
            }
        }
    }

    __shared__ float sm[8];
    #pragma unroll
    for (int o = 16; o; o >>= 1) lmax = fmaxf(lmax, __shfl_xor_sync(0xffffffffu, lmax, o));
    if (lane == 0) sm[wl] = lmax;
    __syncthreads();
    if (threadIdx.x == 0) {
        float m = sm[0];
        #pragma unroll
        for (int i = 1; i < 8; i++) m = fmaxf(m, sm[i]);
        d_partial[blockIdx.x] = m;
    }
}

// ---------------------------------------------------------------------------
__global__ __launch_bounds__(256)
void k_expsum(int E, int nmax) {
    __shared__ float red[8];
    __shared__ float s_gmax;
    float m = -3.402823466e38f;
    for (int i = threadIdx.x; i < nmax; i += blockDim.x) m = fmaxf(m, d_partial[i]);
    #pragma unroll
    for (int o = 16; o; o >>= 1) m = fmaxf(m, __shfl_xor_sync(0xffffffffu, m, o));
    if ((threadIdx.x & 31) == 0) red[threadIdx.x >> 5] = m;
    __syncthreads();
    if (threadIdx.x == 0) {
        float v = red[0];
        #pragma unroll
        for (int i = 1; i < 8; i++) v = fmaxf(v, red[i]);
        s_gmax = v;
    }
    __syncthreads();
    float gmax = s_gmax;

    float s = 0.f;
    int stride = gridDim.x * blockDim.x;
    for (int i = blockIdx.x * blockDim.x + threadIdx.x; i < E; i += stride)
        s += expf(__ldcs(&d_logits[i]) - gmax);
    __syncthreads();
    #pragma unroll
    for (int o = 16; o; o >>= 1) s += __shfl_xor_sync(0xffffffffu, s, o);
    if ((threadIdx.x & 31) == 0) red[threadIdx.x >> 5] = s;
    __syncthreads();
    if (threadIdx.x == 0) {
        float t = 0.f;
        #pragma unroll
        for (int i = 0; i < 8; i++) t += red[i];
        d_partial2[blockIdx.x] = t;
    }
}

__global__ __launch_bounds__(256)
void k_write(float* __restrict__ out, int E, int nmax, int nsum) {
    __shared__ float red[8];
    __shared__ float s_gmax, s_inv;
    float m = -3.402823466e38f;
    for (int i = threadIdx.x; i < nmax; i += blockDim.x) m = fmaxf(m, d_partial[i]);
    #pragma unroll
    for (int o = 16; o; o >>= 1) m = fmaxf(m, __shfl_xor_sync(0xffffffffu, m, o));
    if ((threadIdx.x & 31) == 0) red[threadIdx.x >> 5] = m;
    __syncthreads();
    if (threadIdx.x == 0) {
        float v = red[0];
        #pragma unroll
        for (int i = 1; i < 8; i++) v = fmaxf(v, red[i]);
        s_gmax = v;
    }
    __syncthreads();
    float gmax = s_gmax;
    __syncthreads();

    float s = 0.f;
    for (int i = threadIdx.x; i < nsum; i += blockDim.x) s += d_partial2[i];
    #pragma unroll
    for (int o = 16; o; o >>= 1) s += __shfl_xor_sync(0xffffffffu, s, o);
    if ((threadIdx.x & 31) == 0) red[threadIdx.x >> 5] = s;
    __syncthreads();
    if (threadIdx.x == 0) {
        float t = 0.f;
        #pragma unroll
        for (int i = 0; i < 8; i++) t += red[i];
        s_inv = 1.f / t;
    }
    __syncthreads();
    float inv = s_inv;

    int stride = gridDim.x * blockDim.x;
    for (int i = blockIdx.x * blockDim.x + threadIdx.x; i < E; i += stride)
        __stcs(&out[i], expf(__ldcs(&d_logits[i]) - gmax) * inv);
}

// ---------------------------------------------------------------------------
extern "C" void kernel_launch(void* const* d_in, const int* in_sizes, int n_in,
                              void* d_out, int out_size) {
    const float*    emb  = (const float*)d_in[0];
    const unsigned* lm32 = (const unsigned*)d_in[1];
    const float*    W1   = (const float*)d_in[2];
    const float*    b1   = (const float*)d_in[3];
    const float*    W2   = (const float*)d_in[4];
    const float*    b2   = (const float*)d_in[5];
    float* out = (float*)d_out;

    int nNodes = in_sizes[0] / HID;
    int E = in_sizes[1] / 2;
    if (nNodes > NMAX) nNodes = NMAX;
    if (E > EMAX) E = EMAX;

    cudaFuncSetAttribute(k_gemm, cudaFuncAttributeMaxDynamicSharedMemorySize, GSMEM);

    int nTiles = (nNodes + 63) / 64;

    k_init<<<1, 1>>>();
    k_detect<<<256, 256>>>(lm32, 2 * E);
    k_prepW<<<64, 256>>>(W1);
    k_gemm<<<nTiles, 256, GSMEM>>>(emb, b1, nNodes);
    k_edges<<<1184, 256>>>(lm32, W2, b2, E);
    k_expsum<<<1024, 256>>>(E, 1184);
    k_write<<<1024, 256>>>(out, E, 1184, 1024);
}